// round 15
// baseline (speedup 1.0000x reference)
#include <cuda_runtime.h>
#include <cuda_bf16.h>
#include <cuda_fp16.h>
#include <cstdint>

// ============================================================================
// Problem constants
// ============================================================================
static constexpr int B_ROWS = 131072;
static constexpr int KC     = 512;
static constexpr int TM     = 128;
static constexpr int NTILES = B_ROWS / TM;   // 1024
static constexpr int NCTAS  = 148;           // persistent grid

static constexpr float LOG2E = 1.4426950408889634f;
static constexpr float LN2   = 0.6931471805599453f;

// ============================================================================
// SMEM layout (bytes) — tile regions 1024-aligned for SW128
// ============================================================================
static constexpr int OFF_ZSQ  = 0;        // 128 f32 (log2e-scaled), parity buf 0
static constexpr int OFF_CSQ  = 512;      // 512 f32 (NEGATED, log2e-scaled)
static constexpr int OFF_W    = 2560;     // 128*9 f32 (chunk running-max snapshots)
static constexpr int OFF_MST  = 7168;     // 4 grp x 128 rows x 4 f32; pad slots of
                                          //   grp0/grp1 hold Mv / inv after merge
static constexpr int OFF_RED  = 15360;    // warp partials + flag + dbl scratch
static constexpr int OFF_ZSQ2 = 15872;    // zsq parity buf 1 (512 B, in RED spare)
static constexpr int OFF_AHI  = 16384;    // z-hi 128x128B = 16 KB
static constexpr int OFF_ALO  = 32768;    // z-lo 16 KB
static constexpr int OFF_ESTG = 49152;    // e-stage: chunk0 rows r2/r3, 32 KB
static constexpr int OFF_BHI  = 81920;    // c-hi  512 x 128B = 64 KB (PERSISTENT)
static constexpr int OFF_BLO  = 147456;   // 64 KB (PERSISTENT)
static constexpr int SMEM_BYTES = 212992; // 208 KB

__device__ float g_loss_partial[NCTAS];
__device__ unsigned int g_done;   // zero-init; reset by last CTA each run

#define SWZ(o) ((o) ^ (((o) >> 3) & 0x70))

// ============================================================================
// Helpers
// ============================================================================
__device__ __forceinline__ uint32_t smem_u32(const void* p) {
    uint32_t a;
    asm("{ .reg .u64 t; cvta.to.shared.u64 t, %1; cvt.u32.u64 %0, t; }" : "=r"(a) : "l"(p));
    return a;
}

__device__ __forceinline__ float ex2f(float x) {   // bare MUFU.EX2 (log2 domain)
    float r;
    asm("ex2.approx.ftz.f32 %0, %1;" : "=f"(r) : "f"(x));
    return r;
}

// ---- packed f32x2 (Blackwell family: double-rate FP32) ---------------------
__device__ __forceinline__ uint64_t pk2(float a, float b) {
    uint64_t r;
    asm("mov.b64 %0, {%1, %2};" : "=l"(r) : "f"(a), "f"(b));
    return r;
}
__device__ __forceinline__ void upk2(float& a, float& b, uint64_t p) {
    asm("mov.b64 {%0, %1}, %2;" : "=f"(a), "=f"(b) : "l"(p));
}
__device__ __forceinline__ uint64_t add2(uint64_t a, uint64_t b) {
    uint64_t r;
    asm("add.rn.f32x2 %0, %1, %2;" : "=l"(r) : "l"(a), "l"(b));
    return r;
}
__device__ __forceinline__ uint64_t mul2(uint64_t a, uint64_t b) {
    uint64_t r;
    asm("mul.rn.f32x2 %0, %1, %2;" : "=l"(r) : "l"(a), "l"(b));
    return r;
}
__device__ __forceinline__ uint64_t fma2(uint64_t a, uint64_t b, uint64_t c) {
    uint64_t r;
    asm("fma.rn.f32x2 %0, %1, %2, %3;" : "=l"(r) : "l"(a), "l"(b), "l"(c));
    return r;
}

__device__ __forceinline__ void ldsm4(uint32_t r[4], uint32_t addr) {
    asm volatile("ldmatrix.sync.aligned.m8n8.x4.shared.b16 {%0,%1,%2,%3}, [%4];"
                 : "=r"(r[0]), "=r"(r[1]), "=r"(r[2]), "=r"(r[3]) : "r"(addr));
}

__device__ __forceinline__ void mma16816(float* d, const uint32_t* a, uint32_t b0, uint32_t b1) {
    asm volatile("mma.sync.aligned.m16n8k16.row.col.f32.bf16.bf16.f32 "
                 "{%0,%1,%2,%3}, {%4,%5,%6,%7}, {%8,%9}, {%0,%1,%2,%3};"
                 : "+f"(d[0]), "+f"(d[1]), "+f"(d[2]), "+f"(d[3])
                 : "r"(a[0]), "r"(a[1]), "r"(a[2]), "r"(a[3]), "r"(b0), "r"(b1));
}

__device__ __forceinline__ void split2(float x, float y, uint32_t& hi, uint32_t& lo) {
    __nv_bfloat16 hx = __float2bfloat16(x), hy = __float2bfloat16(y);
    float rx = x - __bfloat162float(hx);
    float ry = y - __bfloat162float(hy);
    __nv_bfloat162 h(hx, hy);
    __nv_bfloat162 l(__float2bfloat16(rx), __float2bfloat16(ry));
    hi = *reinterpret_cast<uint32_t*>(&h);
    lo = *reinterpret_cast<uint32_t*>(&l);
}

__device__ __forceinline__ void sts32(uint32_t addr, uint32_t v) {
    asm volatile("st.shared.b32 [%0], %1;" :: "r"(addr), "r"(v) : "memory");
}
__device__ __forceinline__ uint32_t lds32(uint32_t addr) {
    uint32_t v;
    asm volatile("ld.shared.b32 %0, [%1];" : "=r"(v) : "r"(addr));
    return v;
}

// One 64-col chunk of cross' for an m32 warp tile (3 split terms fused).
// acc[64]: [0..31] rows r0/r1, [32..63] rows r2/r3.
__device__ __forceinline__ void compute_chunk(
    float acc[64], uint32_t sb, uint32_t chbase,
    uint32_t aoff0, uint32_t aoff1, uint32_t bRowL, uint32_t bK16)
{
    #pragma unroll
    for (int i = 0; i < 64; i++) acc[i] = 0.f;
    #pragma unroll
    for (int ks = 0; ks < 4; ks++) {
        uint32_t a0[4], a1[4], l0[4], l1[4];
        ldsm4(a0, sb + OFF_AHI + SWZ(aoff0 + ks * 32));
        ldsm4(a1, sb + OFF_AHI + SWZ(aoff1 + ks * 32));
        ldsm4(l0, sb + OFF_ALO + SWZ(aoff0 + ks * 32));
        ldsm4(l1, sb + OFF_ALO + SWZ(aoff1 + ks * 32));
        #pragma unroll
        for (int p = 0; p < 4; p++) {
            const uint32_t bo = (chbase + p * 16 + bRowL) * 128 + bK16 + ks * 32;
            uint32_t bh[4], bl[4];
            ldsm4(bh, sb + OFF_BHI + SWZ(bo));
            ldsm4(bl, sb + OFF_BLO + SWZ(bo));
            float* A0 = acc + (p * 2) * 4;
            float* A1 = acc + (p * 2 + 1) * 4;
            float* B0 = acc + 32 + (p * 2) * 4;
            float* B1 = acc + 32 + (p * 2 + 1) * 4;
            mma16816(A0, a0, bh[0], bh[1]); mma16816(A1, a0, bh[2], bh[3]);
            mma16816(A0, a0, bl[0], bl[1]); mma16816(A1, a0, bl[2], bl[3]);
            mma16816(A0, l0, bh[0], bh[1]); mma16816(A1, l0, bh[2], bh[3]);
            mma16816(B0, a1, bh[0], bh[1]); mma16816(B1, a1, bh[2], bh[3]);
            mma16816(B0, a1, bl[0], bl[1]); mma16816(B1, a1, bl[2], bl[3]);
            mma16816(B0, l1, bh[0], bh[1]); mma16816(B1, l1, bh[2], bh[3]);
        }
    }
}

// ============================================================================
// Persistent kernel: 148 CTAs x 512 threads (16 warps)
// warp = m32-tile (mt = wid&3) x n128 col-group (grp = wid>>2, chunks 2g,2g+1)
// Pipelined tile loop: next-tile z split overlaps merge; NO loop-top barrier —
// warps flow pass2(t) -> pass1(t+1) freely. 2 barriers/tile. zsq double-buffered.
// ============================================================================
__global__ void __launch_bounds__(512, 1)
soft_kmeans_kernel(const float* __restrict__ z, const float* __restrict__ cc,
                   float* __restrict__ q_out, float* __restrict__ loss_out) {
    extern __shared__ char smem[];
    const uint32_t sb = smem_u32(smem);
    const int tid  = threadIdx.x;
    const int lane = tid & 31;
    const int wid  = tid >> 5;
    const int bid  = blockIdx.x;
    const int mt   = wid & 3;     // rows mt*32 .. mt*32+31
    const int grp  = wid >> 2;    // cols grp*128 .. grp*128+127

    float* zsqA  = reinterpret_cast<float*>(smem + OFF_ZSQ);
    float* zsqB  = reinterpret_cast<float*>(smem + OFF_ZSQ2);
    float* csq_s = reinterpret_cast<float*>(smem + OFF_CSQ);
    float* w_s   = reinterpret_cast<float*>(smem + OFF_W);
    float* mst_s = reinterpret_cast<float*>(smem + OFF_MST);
    float* red_s = reinterpret_cast<float*>(smem + OFF_RED);
    unsigned int* flag_s = reinterpret_cast<unsigned int*>(smem + OFF_RED + 64);

    const float4* z4 = reinterpret_cast<const float4*>(z);
    const float SC = 2.0f * LOG2E;

    // ---- split all 512 centers ONCE (persistent for all tiles) -------------
    {
        const float4* ct = reinterpret_cast<const float4*>(cc);
        #pragma unroll 4
        for (int it = 0; it < 16; it++) {
            const int idx = it * 512 + tid;
            const int row = idx >> 4, c4 = idx & 15;
            const float4 v = ct[idx];
            float sq = v.x * v.x + v.y * v.y + v.z * v.z + v.w * v.w;
            sq += __shfl_xor_sync(~0u, sq, 1);
            sq += __shfl_xor_sync(~0u, sq, 2);
            sq += __shfl_xor_sync(~0u, sq, 4);
            sq += __shfl_xor_sync(~0u, sq, 8);
            if ((lane & 15) == 0) csq_s[row] = -sq * LOG2E;  // ready-to-add addend
            uint2 hi, lo;
            split2(v.x, v.y, hi.x, lo.x);
            split2(v.z, v.w, hi.y, lo.y);
            const uint32_t so = SWZ((uint32_t)(row * 128 + c4 * 8));
            *reinterpret_cast<uint2*>(smem + OFF_BHI + so) = hi;
            *reinterpret_cast<uint2*>(smem + OFF_BLO + so) = lo;
        }
    }

    // ---- prologue: split first z tile into A, zsq buf 0 ---------------------
    {
        const float4* zt = z4 + (size_t)bid * 2048;
        #pragma unroll
        for (int it = 0; it < 4; it++) {
            const int idx = it * 512 + tid;
            const int row = idx >> 4, c4 = idx & 15;
            const float4 v = zt[idx];
            float sq = v.x * v.x + v.y * v.y + v.z * v.z + v.w * v.w;
            sq += __shfl_xor_sync(~0u, sq, 1);
            sq += __shfl_xor_sync(~0u, sq, 2);
            sq += __shfl_xor_sync(~0u, sq, 4);
            sq += __shfl_xor_sync(~0u, sq, 8);
            if ((lane & 15) == 0) zsqA[row] = sq * LOG2E;
            uint2 hi, lo;
            split2(SC * v.x, SC * v.y, hi.x, lo.x);
            split2(SC * v.z, SC * v.w, hi.y, lo.y);
            const uint32_t so = SWZ((uint32_t)(row * 128 + c4 * 8));
            *reinterpret_cast<uint2*>(smem + OFF_AHI + so) = hi;
            *reinterpret_cast<uint2*>(smem + OFF_ALO + so) = lo;
        }
    }
    __syncthreads();   // B + first A/zsq visible

    // ---- lane decodes (m32 tile) -------------------------------------------
    const uint32_t aCol16 = ((lane >> 4) & 1) * 16;
    const uint32_t aRow0  = (uint32_t)(mt * 32 + ((lane >> 3) & 1) * 8 + (lane & 7));
    const uint32_t aoff0  = aRow0 * 128 + aCol16;
    const uint32_t aoff1  = (aRow0 + 16) * 128 + aCol16;
    const uint32_t bRowL  = ((lane >> 4) & 1) * 8 + (lane & 7);
    const uint32_t bK16   = ((lane >> 3) & 1) * 16;

    const int r0 = mt * 32 + (lane >> 2);   // r1=r0+8, r2=r0+16, r3=r0+24
    const uint32_t estg = sb + OFF_ESTG + (uint32_t)tid * 4;  // slot stride 2048

    float cta_loss = 0.f;
    int par = 0;

    // ======================= tile loop =====================================
    for (int tile = bid; tile < NTILES; tile += NCTAS) {

        // ---- PASS 1: 2 chunks of 64 cols; 4 row streams; e -> hp/SMEM ------
        float m0, s0 = 0.f, t0 = 0.f;
        float m1, s1 = 0.f, t1 = 0.f;
        float m2, s2 = 0.f, t2 = 0.f;
        float m3, s3 = 0.f, t3 = 0.f;
        uint32_t hp[48];

        #pragma unroll
        for (int ci = 0; ci < 2; ci++) {
            const uint32_t chbase = (uint32_t)(grp * 128 + ci * 64);

            float acc[64];
            compute_chunk(acc, sb, chbase, aoff0, aoff1, bRowL, bK16);

            // u = cross' + (-csq'); chunk max per row stream
            float cm0 = -1e30f, cm1 = -1e30f, cm2 = -1e30f, cm3 = -1e30f;
            #pragma unroll
            for (int nt = 0; nt < 8; nt++) {
                const float2 cs = *reinterpret_cast<const float2*>(
                    csq_s + chbase + nt * 8 + (lane & 3) * 2);
                float* A = acc + nt * 4;
                float* B = acc + 32 + nt * 4;
                A[0] += cs.x;  A[1] += cs.y;   // r0
                A[2] += cs.x;  A[3] += cs.y;   // r1
                B[0] += cs.x;  B[1] += cs.y;   // r2
                B[2] += cs.x;  B[3] += cs.y;   // r3
                cm0 = fmaxf(cm0, fmaxf(A[0], A[1]));
                cm1 = fmaxf(cm1, fmaxf(A[2], A[3]));
                cm2 = fmaxf(cm2, fmaxf(B[0], B[1]));
                cm3 = fmaxf(cm3, fmaxf(B[2], B[3]));
            }
            cm0 = fmaxf(cm0, __shfl_xor_sync(~0u, cm0, 1));
            cm0 = fmaxf(cm0, __shfl_xor_sync(~0u, cm0, 2));
            cm1 = fmaxf(cm1, __shfl_xor_sync(~0u, cm1, 1));
            cm1 = fmaxf(cm1, __shfl_xor_sync(~0u, cm1, 2));
            cm2 = fmaxf(cm2, __shfl_xor_sync(~0u, cm2, 1));
            cm2 = fmaxf(cm2, __shfl_xor_sync(~0u, cm2, 2));
            cm3 = fmaxf(cm3, __shfl_xor_sync(~0u, cm3, 1));
            cm3 = fmaxf(cm3, __shfl_xor_sync(~0u, cm3, 2));
            if (ci == 0) {
                m0 = cm0; m1 = cm1; m2 = cm2; m3 = cm3;  // s=t=0, no rescale
            } else {
                const float nm0 = fmaxf(m0, cm0), f0 = ex2f(m0 - nm0);
                const float nm1 = fmaxf(m1, cm1), f1 = ex2f(m1 - nm1);
                const float nm2 = fmaxf(m2, cm2), f2 = ex2f(m2 - nm2);
                const float nm3 = fmaxf(m3, cm3), f3 = ex2f(m3 - nm3);
                s0 *= f0; t0 *= f0; m0 = nm0;
                s1 *= f1; t1 *= f1; m1 = nm1;
                s2 *= f2; t2 *= f2; m2 = nm2;
                s3 *= f3; t3 *= f3; m3 = nm3;
            }

            // ---- packed-f32x2 e-loop: chunk-local (sL, tL') accumulators ----
            uint64_t sL0 = 0, sL1 = 0, sL2 = 0, sL3 = 0;
            uint64_t tL0 = 0, tL1 = 0, tL2 = 0, tL3 = 0;
            const uint64_t nmp0 = pk2(-m0, -m0);
            const uint64_t nmp1 = pk2(-m1, -m1);
            const uint64_t nmp2 = pk2(-m2, -m2);
            const uint64_t nmp3 = pk2(-m3, -m3);
            #pragma unroll
            for (int nt = 0; nt < 8; nt++) {
                float* A = acc + nt * 4;
                float* B = acc + 32 + nt * 4;
                const uint64_t u0 = add2(pk2(A[0], A[1]), nmp0);
                const uint64_t u1 = add2(pk2(A[2], A[3]), nmp1);
                const uint64_t u2 = add2(pk2(B[0], B[1]), nmp2);
                const uint64_t u3 = add2(pk2(B[2], B[3]), nmp3);
                float a0, b0, a1, b1, a2, b2, a3, b3;
                upk2(a0, b0, u0);  upk2(a1, b1, u1);
                upk2(a2, b2, u2);  upk2(a3, b3, u3);
                const float e00 = ex2f(a0), e01 = ex2f(b0);
                const float e10 = ex2f(a1), e11 = ex2f(b1);
                const float e20 = ex2f(a2), e21 = ex2f(b2);
                const float e30 = ex2f(a3), e31 = ex2f(b3);
                const uint64_t ep0 = pk2(e00, e01);
                const uint64_t ep1 = pk2(e10, e11);
                const uint64_t ep2 = pk2(e20, e21);
                const uint64_t ep3 = pk2(e30, e31);
                sL0 = add2(sL0, ep0);  tL0 = fma2(ep0, u0, tL0);
                sL1 = add2(sL1, ep1);  tL1 = fma2(ep1, u1, tL1);
                sL2 = add2(sL2, ep2);  tL2 = fma2(ep2, u2, tL2);
                sL3 = add2(sL3, ep3);  tL3 = fma2(ep3, u3, tL3);
                const __half2 h0 = __floats2half2_rn(e00, e01);
                const __half2 h1 = __floats2half2_rn(e10, e11);
                const __half2 h2 = __floats2half2_rn(e20, e21);
                const __half2 h3 = __floats2half2_rn(e30, e31);
                if (ci == 0) {
                    hp[nt]     = *reinterpret_cast<const uint32_t*>(&h0);
                    hp[8 + nt] = *reinterpret_cast<const uint32_t*>(&h1);
                    sts32(estg + (uint32_t)((nt * 2) * 2048),
                          *reinterpret_cast<const uint32_t*>(&h2));
                    sts32(estg + (uint32_t)((nt * 2 + 1) * 2048),
                          *reinterpret_cast<const uint32_t*>(&h3));
                } else {
                    hp[16 + nt] = *reinterpret_cast<const uint32_t*>(&h0);
                    hp[24 + nt] = *reinterpret_cast<const uint32_t*>(&h1);
                    hp[32 + nt] = *reinterpret_cast<const uint32_t*>(&h2);
                    hp[40 + nt] = *reinterpret_cast<const uint32_t*>(&h3);
                }
            }
            // fold chunk-local sums into running (m-corrected t)
            {
                float xa, xb, ya, yb;
                upk2(xa, xb, sL0); upk2(ya, yb, tL0);
                const float sl = xa + xb;
                s0 += sl;  t0 += ya + yb + m0 * sl;
                upk2(xa, xb, sL1); upk2(ya, yb, tL1);
                const float sl1v = xa + xb;
                s1 += sl1v;  t1 += ya + yb + m1 * sl1v;
                upk2(xa, xb, sL2); upk2(ya, yb, tL2);
                const float sl2v = xa + xb;
                s2 += sl2v;  t2 += ya + yb + m2 * sl2v;
                upk2(xa, xb, sL3); upk2(ya, yb, tL3);
                const float sl3v = xa + xb;
                s3 += sl3v;  t3 += ya + yb + m3 * sl3v;
            }
            if ((lane & 3) == 0) {
                const int ch = grp * 2 + ci;
                w_s[r0 * 9 + ch]        = m0;
                w_s[(r0 + 8) * 9 + ch]  = m1;
                w_s[(r0 + 16) * 9 + ch] = m2;
                w_s[(r0 + 24) * 9 + ch] = m3;
            }
        }

        // ---- group-local row reductions + publish (m, s, t_u) --------------
        s0 += __shfl_xor_sync(~0u, s0, 1);  s0 += __shfl_xor_sync(~0u, s0, 2);
        t0 += __shfl_xor_sync(~0u, t0, 1);  t0 += __shfl_xor_sync(~0u, t0, 2);
        s1 += __shfl_xor_sync(~0u, s1, 1);  s1 += __shfl_xor_sync(~0u, s1, 2);
        t1 += __shfl_xor_sync(~0u, t1, 1);  t1 += __shfl_xor_sync(~0u, t1, 2);
        s2 += __shfl_xor_sync(~0u, s2, 1);  s2 += __shfl_xor_sync(~0u, s2, 2);
        t2 += __shfl_xor_sync(~0u, t2, 1);  t2 += __shfl_xor_sync(~0u, t2, 2);
        s3 += __shfl_xor_sync(~0u, s3, 1);  s3 += __shfl_xor_sync(~0u, s3, 2);
        t3 += __shfl_xor_sync(~0u, t3, 1);  t3 += __shfl_xor_sync(~0u, t3, 2);
        if ((lane & 3) == 0) {
            float* p0 = mst_s + (size_t)(grp * 128 + r0) * 4;
            p0[0] = m0; p0[1] = s0; p0[2] = t0;
            float* p1 = mst_s + (size_t)(grp * 128 + r0 + 8) * 4;
            p1[0] = m1; p1[1] = s1; p1[2] = t1;
            float* p2 = mst_s + (size_t)(grp * 128 + r0 + 16) * 4;
            p2[0] = m2; p2[1] = s2; p2[2] = t2;
            float* p3 = mst_s + (size_t)(grp * 128 + r0 + 24) * 4;
            p3[0] = m3; p3[1] = s3; p3[2] = t3;
        }
        __syncthreads();   // sync2: mst published; A region + zsq[par^1] now dead

        // ---- issue next-tile z loads (latency hidden under merge) ----------
        const int ntile = tile + NCTAS;
        float4 v0, v1, v2, v3;
        if (ntile < NTILES) {
            const float4* zt = z4 + (size_t)ntile * 2048;
            v0 = zt[tid];
            v1 = zt[512 + tid];
            v2 = zt[1024 + tid];
            v3 = zt[1536 + tid];
        }

        // ---- merge 4 groups per row (thread = row): Mv, inv, loss only -----
        float lossr = 0.f;
        {
            const float* zcur = par ? zsqB : zsqA;
            if (tid < TM) {
                float Mv = -1e30f;
                float mg[4], sg[4], tg[4];
                #pragma unroll
                for (int g = 0; g < 4; g++) {
                    const float* p = mst_s + (size_t)(g * 128 + tid) * 4;
                    mg[g] = p[0]; sg[g] = p[1]; tg[g] = p[2];
                    Mv = fmaxf(Mv, mg[g]);
                }
                float sF = 0.f, tF = 0.f;
                #pragma unroll
                for (int g = 0; g < 4; g++) {
                    const float f = ex2f(mg[g] - Mv);
                    sF += sg[g] * f; tF += tg[g] * f;
                }
                const float inv = 1.f / sF;
                lossr = (zcur[tid] - tF * inv) * LN2;
                mst_s[(size_t)tid * 4 + 3]         = Mv;    // pad slot of grp0 row
                mst_s[(size_t)(128 + tid) * 4 + 3] = inv;   // pad slot of grp1 row
            }
        }
        #pragma unroll
        for (int o = 16; o; o >>= 1) lossr += __shfl_xor_sync(~0u, lossr, o);
        if (wid < 4 && lane == 0) red_s[wid] = lossr;

        // ---- consume next-tile z: split into A hi/lo + zsq[par^1] ----------
        if (ntile < NTILES) {
            float* znext = par ? zsqA : zsqB;
            float4 vv[4] = {v0, v1, v2, v3};
            #pragma unroll
            for (int it = 0; it < 4; it++) {
                const int idx = it * 512 + tid;
                const int row = idx >> 4, c4 = idx & 15;
                const float4 v = vv[it];
                float sq = v.x * v.x + v.y * v.y + v.z * v.z + v.w * v.w;
                sq += __shfl_xor_sync(~0u, sq, 1);
                sq += __shfl_xor_sync(~0u, sq, 2);
                sq += __shfl_xor_sync(~0u, sq, 4);
                sq += __shfl_xor_sync(~0u, sq, 8);
                if ((lane & 15) == 0) znext[row] = sq * LOG2E;
                uint2 hi, lo;
                split2(SC * v.x, SC * v.y, hi.x, lo.x);
                split2(SC * v.z, SC * v.w, hi.y, lo.y);
                const uint32_t so = SWZ((uint32_t)(row * 128 + c4 * 8));
                *reinterpret_cast<uint2*>(smem + OFF_AHI + so) = hi;
                *reinterpret_cast<uint2*>(smem + OFF_ALO + so) = lo;
            }
        }
        __syncthreads();   // sync3: Mv/inv + red_s + next A/zsq all visible
        if (tid == 0)
            cta_loss += red_s[0] + red_s[1] + red_s[2] + red_s[3];

        // ---- PASS 2: q stores, packed e*w (does NOT read A) ----------------
        {
            float* qt = q_out + (size_t)tile * TM * KC;
            const int c2 = (lane & 3) * 2;
            float Mvj[4], ivj[4];
            #pragma unroll
            for (int j = 0; j < 4; j++) {
                const int r = r0 + j * 8;
                Mvj[j] = mst_s[(size_t)r * 4 + 3];
                ivj[j] = mst_s[(size_t)(128 + r) * 4 + 3];
            }
            #pragma unroll
            for (int ci = 0; ci < 2; ci++) {
                const int ch = grp * 2 + ci;
                const int colb = grp * 128 + ci * 64 + c2;
                const float w0 = ex2f(w_s[r0 * 9 + ch]        - Mvj[0]) * ivj[0];
                const float w1 = ex2f(w_s[(r0 + 8) * 9 + ch]  - Mvj[1]) * ivj[1];
                const float w2 = ex2f(w_s[(r0 + 16) * 9 + ch] - Mvj[2]) * ivj[2];
                const float w3 = ex2f(w_s[(r0 + 24) * 9 + ch] - Mvj[3]) * ivj[3];
                const uint64_t wp0 = pk2(w0, w0);
                const uint64_t wp1 = pk2(w1, w1);
                const uint64_t wp2 = pk2(w2, w2);
                const uint64_t wp3 = pk2(w3, w3);
                #pragma unroll
                for (int nt = 0; nt < 8; nt++) {
                    uint32_t u0, u1, u2, u3;
                    if (ci == 0) {
                        u0 = hp[nt];  u1 = hp[8 + nt];
                        u2 = lds32(estg + (uint32_t)((nt * 2) * 2048));
                        u3 = lds32(estg + (uint32_t)((nt * 2 + 1) * 2048));
                    } else {
                        u0 = hp[16 + nt]; u1 = hp[24 + nt];
                        u2 = hp[32 + nt]; u3 = hp[40 + nt];
                    }
                    const float2 e0 = __half22float2(*reinterpret_cast<const __half2*>(&u0));
                    const float2 e1 = __half22float2(*reinterpret_cast<const __half2*>(&u1));
                    const float2 e2 = __half22float2(*reinterpret_cast<const __half2*>(&u2));
                    const float2 e3 = __half22float2(*reinterpret_cast<const __half2*>(&u3));
                    const uint64_t o0 = mul2(pk2(e0.x, e0.y), wp0);
                    const uint64_t o1 = mul2(pk2(e1.x, e1.y), wp1);
                    const uint64_t o2 = mul2(pk2(e2.x, e2.y), wp2);
                    const uint64_t o3 = mul2(pk2(e3.x, e3.y), wp3);
                    *reinterpret_cast<uint64_t*>(qt + (size_t)r0 * KC + colb + nt * 8) = o0;
                    *reinterpret_cast<uint64_t*>(qt + (size_t)(r0 + 8) * KC + colb + nt * 8) = o1;
                    *reinterpret_cast<uint64_t*>(qt + (size_t)(r0 + 16) * KC + colb + nt * 8) = o2;
                    *reinterpret_cast<uint64_t*>(qt + (size_t)(r0 + 24) * KC + colb + nt * 8) = o3;
                }
            }
        }
        par ^= 1;
        // no barrier here: pass1(t+1) reads A (ready since sync3) and B only;
        // w_s/ESTG rewrites in pass1(t+1) are same-warp/thread-private vs pass2(t).
    } // tile loop

    if (tid == 0) g_loss_partial[bid] = cta_loss;

    // ---- last-CTA loss finalize (deterministic fixed-order sum) ------------
    __threadfence();
    if (tid == 0) {
        const unsigned int old = atomicAdd(&g_done, 1u);
        *flag_s = (old == (unsigned int)(NCTAS - 1)) ? 1u : 0u;
    }
    __syncthreads();
    if (*flag_s) {
        double a = (tid < NCTAS) ? (double)g_loss_partial[tid] : 0.0;
        #pragma unroll
        for (int o = 16; o; o >>= 1) a += __shfl_xor_sync(~0u, a, o);
        double* dred = reinterpret_cast<double*>(smem + OFF_RED + 128);
        if (lane == 0) dred[wid] = a;
        __syncthreads();
        if (tid == 0) {
            double t = 0.0;
            #pragma unroll
            for (int i = 0; i < 16; i++) t += dred[i];
            if (loss_out) *loss_out = (float)(t / (double)B_ROWS);
            g_done = 0;   // reset for next graph replay
        }
    }
}

// ============================================================================
// Launch
// ============================================================================
extern "C" void kernel_launch(void* const* d_in, const int* in_sizes, int n_in,
                              void* d_out, int out_size) {
    const float* z  = (const float*)d_in[0];
    const float* cc = (const float*)d_in[1];
    float* q = (float*)d_out;

    const long long q_elems = (long long)B_ROWS * KC;  // 67108864
    float* loss_out = ((long long)out_size > q_elems) ? (q + q_elems) : nullptr;

    cudaFuncSetAttribute(soft_kmeans_kernel,
                         cudaFuncAttributeMaxDynamicSharedMemorySize, SMEM_BYTES);
    soft_kmeans_kernel<<<NCTAS, 512, SMEM_BYTES>>>(z, cc, q, loss_out);
}

// round 16
// speedup vs baseline: 1.0626x; 1.0626x over previous
#include <cuda_runtime.h>
#include <cuda_bf16.h>
#include <cuda_fp16.h>
#include <cstdint>

// ============================================================================
// Problem constants
// ============================================================================
static constexpr int B_ROWS = 131072;
static constexpr int KC     = 512;
static constexpr int TM     = 128;
static constexpr int NTILES = B_ROWS / TM;   // 1024
static constexpr int NCTAS  = 148;           // persistent grid

static constexpr float LOG2E = 1.4426950408889634f;
static constexpr float LN2   = 0.6931471805599453f;

// ============================================================================
// SMEM layout (bytes) — tile regions 1024-aligned for SW128
// ============================================================================
static constexpr int OFF_ZSQ  = 0;        // 128 f32 (log2e-scaled)
static constexpr int OFF_CSQ  = 512;      // 512 f32 (NEGATED, log2e-scaled)
static constexpr int OFF_W    = 2560;     // 128*9 f32 (chunk running-max snapshots)
static constexpr int OFF_MST  = 7168;     // 4 grp x 128 rows x 4 f32; pad slots of
                                          //   grp0/grp1 hold Mv / inv after merge
static constexpr int OFF_RED  = 15360;    // warp partials + flag + dbl scratch (1 KB)
static constexpr int OFF_AHI  = 16384;    // z-hi 128x128B = 16 KB
static constexpr int OFF_ALO  = 32768;    // z-lo 16 KB
static constexpr int OFF_ESTG = 49152;    // e-stage: chunk0 rows r2/r3, 32 KB
static constexpr int OFF_BHI  = 81920;    // c-hi  512 x 128B = 64 KB (PERSISTENT)
static constexpr int OFF_BLO  = 147456;   // 64 KB (PERSISTENT)
static constexpr int SMEM_BYTES = 212992; // 208 KB

__device__ float g_loss_partial[NCTAS];
__device__ unsigned int g_done;   // zero-init; reset by last CTA each run

#define SWZ(o) ((o) ^ (((o) >> 3) & 0x70))

// ============================================================================
// Helpers
// ============================================================================
__device__ __forceinline__ uint32_t smem_u32(const void* p) {
    uint32_t a;
    asm("{ .reg .u64 t; cvta.to.shared.u64 t, %1; cvt.u32.u64 %0, t; }" : "=r"(a) : "l"(p));
    return a;
}

__device__ __forceinline__ float ex2f(float x) {   // bare MUFU.EX2 (log2 domain)
    float r;
    asm("ex2.approx.ftz.f32 %0, %1;" : "=f"(r) : "f"(x));
    return r;
}

// ---- packed f32x2 (Blackwell family: double-rate FP32) ---------------------
__device__ __forceinline__ uint64_t pk2(float a, float b) {
    uint64_t r;
    asm("mov.b64 %0, {%1, %2};" : "=l"(r) : "f"(a), "f"(b));
    return r;
}
__device__ __forceinline__ void upk2(float& a, float& b, uint64_t p) {
    asm("mov.b64 {%0, %1}, %2;" : "=f"(a), "=f"(b) : "l"(p));
}
__device__ __forceinline__ uint64_t add2(uint64_t a, uint64_t b) {
    uint64_t r;
    asm("add.rn.f32x2 %0, %1, %2;" : "=l"(r) : "l"(a), "l"(b));
    return r;
}
__device__ __forceinline__ uint64_t mul2(uint64_t a, uint64_t b) {
    uint64_t r;
    asm("mul.rn.f32x2 %0, %1, %2;" : "=l"(r) : "l"(a), "l"(b));
    return r;
}
__device__ __forceinline__ uint64_t fma2(uint64_t a, uint64_t b, uint64_t c) {
    uint64_t r;
    asm("fma.rn.f32x2 %0, %1, %2, %3;" : "=l"(r) : "l"(a), "l"(b), "l"(c));
    return r;
}

__device__ __forceinline__ void ldsm4(uint32_t r[4], uint32_t addr) {
    asm volatile("ldmatrix.sync.aligned.m8n8.x4.shared.b16 {%0,%1,%2,%3}, [%4];"
                 : "=r"(r[0]), "=r"(r[1]), "=r"(r[2]), "=r"(r[3]) : "r"(addr));
}

__device__ __forceinline__ void mma16816(float* d, const uint32_t* a, uint32_t b0, uint32_t b1) {
    asm volatile("mma.sync.aligned.m16n8k16.row.col.f32.bf16.bf16.f32 "
                 "{%0,%1,%2,%3}, {%4,%5,%6,%7}, {%8,%9}, {%0,%1,%2,%3};"
                 : "+f"(d[0]), "+f"(d[1]), "+f"(d[2]), "+f"(d[3])
                 : "r"(a[0]), "r"(a[1]), "r"(a[2]), "r"(a[3]), "r"(b0), "r"(b1));
}

__device__ __forceinline__ void split2(float x, float y, uint32_t& hi, uint32_t& lo) {
    __nv_bfloat16 hx = __float2bfloat16(x), hy = __float2bfloat16(y);
    float rx = x - __bfloat162float(hx);
    float ry = y - __bfloat162float(hy);
    __nv_bfloat162 h(hx, hy);
    __nv_bfloat162 l(__float2bfloat16(rx), __float2bfloat16(ry));
    hi = *reinterpret_cast<uint32_t*>(&h);
    lo = *reinterpret_cast<uint32_t*>(&l);
}

__device__ __forceinline__ void sts32(uint32_t addr, uint32_t v) {
    asm volatile("st.shared.b32 [%0], %1;" :: "r"(addr), "r"(v) : "memory");
}
__device__ __forceinline__ uint32_t lds32(uint32_t addr) {
    uint32_t v;
    asm volatile("ld.shared.b32 %0, [%1];" : "=r"(v) : "r"(addr));
    return v;
}
__device__ __forceinline__ void stg_cs64(void* p, uint64_t v) {   // evict-first store
    asm volatile("st.global.cs.b64 [%0], %1;" :: "l"(p), "l"(v) : "memory");
}

// One 64-col chunk of cross' for an m32 warp tile (3 split terms fused).
// acc[64]: [0..31] rows r0/r1, [32..63] rows r2/r3.
// MMA issue order interleaves the 4 accumulator streams (A0,A1,B0,B1) so each
// stream's dependent MMAs are 3 apart -> 4 independent tensor chains in flight.
__device__ __forceinline__ void compute_chunk(
    float acc[64], uint32_t sb, uint32_t chbase,
    uint32_t aoff0, uint32_t aoff1, uint32_t bRowL, uint32_t bK16)
{
    #pragma unroll
    for (int i = 0; i < 64; i++) acc[i] = 0.f;
    #pragma unroll
    for (int ks = 0; ks < 4; ks++) {
        uint32_t a0[4], a1[4], l0[4], l1[4];
        ldsm4(a0, sb + OFF_AHI + SWZ(aoff0 + ks * 32));
        ldsm4(a1, sb + OFF_AHI + SWZ(aoff1 + ks * 32));
        ldsm4(l0, sb + OFF_ALO + SWZ(aoff0 + ks * 32));
        ldsm4(l1, sb + OFF_ALO + SWZ(aoff1 + ks * 32));
        #pragma unroll
        for (int p = 0; p < 4; p++) {
            const uint32_t bo = (chbase + p * 16 + bRowL) * 128 + bK16 + ks * 32;
            uint32_t bh[4], bl[4];
            ldsm4(bh, sb + OFF_BHI + SWZ(bo));
            ldsm4(bl, sb + OFF_BLO + SWZ(bo));
            float* A0 = acc + (p * 2) * 4;
            float* A1 = acc + (p * 2 + 1) * 4;
            float* B0 = acc + 32 + (p * 2) * 4;
            float* B1 = acc + 32 + (p * 2 + 1) * 4;
            // term hi*hi (both halves of the warp tile)
            mma16816(A0, a0, bh[0], bh[1]); mma16816(A1, a0, bh[2], bh[3]);
            mma16816(B0, a1, bh[0], bh[1]); mma16816(B1, a1, bh[2], bh[3]);
            // term hi*lo
            mma16816(A0, a0, bl[0], bl[1]); mma16816(A1, a0, bl[2], bl[3]);
            mma16816(B0, a1, bl[0], bl[1]); mma16816(B1, a1, bl[2], bl[3]);
            // term lo*hi
            mma16816(A0, l0, bh[0], bh[1]); mma16816(A1, l0, bh[2], bh[3]);
            mma16816(B0, l1, bh[0], bh[1]); mma16816(B1, l1, bh[2], bh[3]);
        }
    }
}

// ============================================================================
// Persistent kernel: 148 CTAs x 512 threads (16 warps)
// warp = m32-tile (mt = wid&3) x n128 col-group (grp = wid>>2, chunks 2g,2g+1)
// e: chunk0 r0/r1 + chunk1 all rows in regs (hp[48]); chunk0 r2/r3 in SMEM.
// epilogue + pass2 use packed f32x2 math; q written with st.global.cs.
// ============================================================================
__global__ void __launch_bounds__(512, 1)
soft_kmeans_kernel(const float* __restrict__ z, const float* __restrict__ cc,
                   float* __restrict__ q_out, float* __restrict__ loss_out) {
    extern __shared__ char smem[];
    const uint32_t sb = smem_u32(smem);
    const int tid  = threadIdx.x;
    const int lane = tid & 31;
    const int wid  = tid >> 5;
    const int bid  = blockIdx.x;
    const int mt   = wid & 3;     // rows mt*32 .. mt*32+31
    const int grp  = wid >> 2;    // cols grp*128 .. grp*128+127

    float* zsq_s = reinterpret_cast<float*>(smem + OFF_ZSQ);
    float* csq_s = reinterpret_cast<float*>(smem + OFF_CSQ);
    float* w_s   = reinterpret_cast<float*>(smem + OFF_W);
    float* mst_s = reinterpret_cast<float*>(smem + OFF_MST);
    float* red_s = reinterpret_cast<float*>(smem + OFF_RED);
    unsigned int* flag_s = reinterpret_cast<unsigned int*>(smem + OFF_RED + 64);

    const float4* z4 = reinterpret_cast<const float4*>(z);

    // ---- L2-prefetch first z tile ------------------------------------------
    {
        const char* pz = reinterpret_cast<const char*>(z4 + (size_t)bid * 2048) + tid * 256;
        asm volatile("prefetch.global.L2 [%0];" :: "l"(pz));
        asm volatile("prefetch.global.L2 [%0];" :: "l"(pz + 128));
    }

    // ---- split all 512 centers ONCE (persistent for all tiles) -------------
    {
        const float4* ct = reinterpret_cast<const float4*>(cc);
        #pragma unroll 4
        for (int it = 0; it < 16; it++) {
            const int idx = it * 512 + tid;
            const int row = idx >> 4, c4 = idx & 15;
            const float4 v = ct[idx];
            float sq = v.x * v.x + v.y * v.y + v.z * v.z + v.w * v.w;
            sq += __shfl_xor_sync(~0u, sq, 1);
            sq += __shfl_xor_sync(~0u, sq, 2);
            sq += __shfl_xor_sync(~0u, sq, 4);
            sq += __shfl_xor_sync(~0u, sq, 8);
            if ((lane & 15) == 0) csq_s[row] = -sq * LOG2E;  // ready-to-add addend
            uint2 hi, lo;
            split2(v.x, v.y, hi.x, lo.x);
            split2(v.z, v.w, hi.y, lo.y);
            const uint32_t so = SWZ((uint32_t)(row * 128 + c4 * 8));
            *reinterpret_cast<uint2*>(smem + OFF_BHI + so) = hi;
            *reinterpret_cast<uint2*>(smem + OFF_BLO + so) = lo;
        }
    }

    // ---- lane decodes (m32 tile) -------------------------------------------
    const uint32_t aCol16 = ((lane >> 4) & 1) * 16;
    const uint32_t aRow0  = (uint32_t)(mt * 32 + ((lane >> 3) & 1) * 8 + (lane & 7));
    const uint32_t aoff0  = aRow0 * 128 + aCol16;
    const uint32_t aoff1  = (aRow0 + 16) * 128 + aCol16;
    const uint32_t bRowL  = ((lane >> 4) & 1) * 8 + (lane & 7);
    const uint32_t bK16   = ((lane >> 3) & 1) * 16;

    const int r0 = mt * 32 + (lane >> 2);   // r1=r0+8, r2=r0+16, r3=r0+24
    const uint32_t estg = sb + OFF_ESTG + (uint32_t)tid * 4;  // slot stride 2048

    float cta_loss = 0.f;

    // ======================= tile loop =====================================
    for (int tile = bid; tile < NTILES; tile += NCTAS) {

        // ---- split z tile: LDG (L2-hot from prefetch) -> A hi/lo -----------
        {
            const float SC = 2.0f * LOG2E;
            const float4* zt = z4 + (size_t)tile * 2048;
            #pragma unroll
            for (int it = 0; it < 4; it++) {
                const int idx = it * 512 + tid;
                const int row = idx >> 4, c4 = idx & 15;
                const float4 v = zt[idx];
                float sq = v.x * v.x + v.y * v.y + v.z * v.z + v.w * v.w;
                sq += __shfl_xor_sync(~0u, sq, 1);
                sq += __shfl_xor_sync(~0u, sq, 2);
                sq += __shfl_xor_sync(~0u, sq, 4);
                sq += __shfl_xor_sync(~0u, sq, 8);
                if ((lane & 15) == 0) zsq_s[row] = sq * LOG2E;   // zq' (log2)
                uint2 hi, lo;
                split2(SC * v.x, SC * v.y, hi.x, lo.x);
                split2(SC * v.z, SC * v.w, hi.y, lo.y);
                const uint32_t so = SWZ((uint32_t)(row * 128 + c4 * 8));
                *reinterpret_cast<uint2*>(smem + OFF_AHI + so) = hi;
                *reinterpret_cast<uint2*>(smem + OFF_ALO + so) = lo;
            }
        }
        __syncthreads();   // sync1: A/zsq visible (covers B on first tile)

        // ---- PASS 1: 2 chunks of 64 cols; 4 row streams; e -> hp/SMEM ------
        float m0, s0 = 0.f, t0 = 0.f;
        float m1, s1 = 0.f, t1 = 0.f;
        float m2, s2 = 0.f, t2 = 0.f;
        float m3, s3 = 0.f, t3 = 0.f;
        uint32_t hp[48];

        #pragma unroll
        for (int ci = 0; ci < 2; ci++) {
            const uint32_t chbase = (uint32_t)(grp * 128 + ci * 64);

            float acc[64];
            compute_chunk(acc, sb, chbase, aoff0, aoff1, bRowL, bK16);

            // u = cross' + (-csq'); chunk max per row stream
            float cm0 = -1e30f, cm1 = -1e30f, cm2 = -1e30f, cm3 = -1e30f;
            #pragma unroll
            for (int nt = 0; nt < 8; nt++) {
                const float2 cs = *reinterpret_cast<const float2*>(
                    csq_s + chbase + nt * 8 + (lane & 3) * 2);
                float* A = acc + nt * 4;
                float* B = acc + 32 + nt * 4;
                A[0] += cs.x;  A[1] += cs.y;   // r0
                A[2] += cs.x;  A[3] += cs.y;   // r1
                B[0] += cs.x;  B[1] += cs.y;   // r2
                B[2] += cs.x;  B[3] += cs.y;   // r3
                cm0 = fmaxf(cm0, fmaxf(A[0], A[1]));
                cm1 = fmaxf(cm1, fmaxf(A[2], A[3]));
                cm2 = fmaxf(cm2, fmaxf(B[0], B[1]));
                cm3 = fmaxf(cm3, fmaxf(B[2], B[3]));
            }
            cm0 = fmaxf(cm0, __shfl_xor_sync(~0u, cm0, 1));
            cm0 = fmaxf(cm0, __shfl_xor_sync(~0u, cm0, 2));
            cm1 = fmaxf(cm1, __shfl_xor_sync(~0u, cm1, 1));
            cm1 = fmaxf(cm1, __shfl_xor_sync(~0u, cm1, 2));
            cm2 = fmaxf(cm2, __shfl_xor_sync(~0u, cm2, 1));
            cm2 = fmaxf(cm2, __shfl_xor_sync(~0u, cm2, 2));
            cm3 = fmaxf(cm3, __shfl_xor_sync(~0u, cm3, 1));
            cm3 = fmaxf(cm3, __shfl_xor_sync(~0u, cm3, 2));
            if (ci == 0) {
                m0 = cm0; m1 = cm1; m2 = cm2; m3 = cm3;  // s=t=0, no rescale
            } else {
                const float nm0 = fmaxf(m0, cm0), f0 = ex2f(m0 - nm0);
                const float nm1 = fmaxf(m1, cm1), f1 = ex2f(m1 - nm1);
                const float nm2 = fmaxf(m2, cm2), f2 = ex2f(m2 - nm2);
                const float nm3 = fmaxf(m3, cm3), f3 = ex2f(m3 - nm3);
                s0 *= f0; t0 *= f0; m0 = nm0;
                s1 *= f1; t1 *= f1; m1 = nm1;
                s2 *= f2; t2 *= f2; m2 = nm2;
                s3 *= f3; t3 *= f3; m3 = nm3;
            }

            // ---- packed-f32x2 e-loop: chunk-local (sL, tL') accumulators ----
            // tL' = sum e*(u-m); fold back t += tL' + m*sL at chunk end.
            uint64_t sL0 = 0, sL1 = 0, sL2 = 0, sL3 = 0;
            uint64_t tL0 = 0, tL1 = 0, tL2 = 0, tL3 = 0;
            const uint64_t nmp0 = pk2(-m0, -m0);
            const uint64_t nmp1 = pk2(-m1, -m1);
            const uint64_t nmp2 = pk2(-m2, -m2);
            const uint64_t nmp3 = pk2(-m3, -m3);
            #pragma unroll
            for (int nt = 0; nt < 8; nt++) {
                float* A = acc + nt * 4;
                float* B = acc + 32 + nt * 4;
                const uint64_t u0 = add2(pk2(A[0], A[1]), nmp0);
                const uint64_t u1 = add2(pk2(A[2], A[3]), nmp1);
                const uint64_t u2 = add2(pk2(B[0], B[1]), nmp2);
                const uint64_t u3 = add2(pk2(B[2], B[3]), nmp3);
                float a0, b0, a1, b1, a2, b2, a3, b3;
                upk2(a0, b0, u0);  upk2(a1, b1, u1);
                upk2(a2, b2, u2);  upk2(a3, b3, u3);
                const float e00 = ex2f(a0), e01 = ex2f(b0);
                const float e10 = ex2f(a1), e11 = ex2f(b1);
                const float e20 = ex2f(a2), e21 = ex2f(b2);
                const float e30 = ex2f(a3), e31 = ex2f(b3);
                const uint64_t ep0 = pk2(e00, e01);
                const uint64_t ep1 = pk2(e10, e11);
                const uint64_t ep2 = pk2(e20, e21);
                const uint64_t ep3 = pk2(e30, e31);
                sL0 = add2(sL0, ep0);  tL0 = fma2(ep0, u0, tL0);
                sL1 = add2(sL1, ep1);  tL1 = fma2(ep1, u1, tL1);
                sL2 = add2(sL2, ep2);  tL2 = fma2(ep2, u2, tL2);
                sL3 = add2(sL3, ep3);  tL3 = fma2(ep3, u3, tL3);
                const __half2 h0 = __floats2half2_rn(e00, e01);
                const __half2 h1 = __floats2half2_rn(e10, e11);
                const __half2 h2 = __floats2half2_rn(e20, e21);
                const __half2 h3 = __floats2half2_rn(e30, e31);
                if (ci == 0) {
                    hp[nt]     = *reinterpret_cast<const uint32_t*>(&h0);
                    hp[8 + nt] = *reinterpret_cast<const uint32_t*>(&h1);
                    sts32(estg + (uint32_t)((nt * 2) * 2048),
                          *reinterpret_cast<const uint32_t*>(&h2));
                    sts32(estg + (uint32_t)((nt * 2 + 1) * 2048),
                          *reinterpret_cast<const uint32_t*>(&h3));
                } else {
                    hp[16 + nt] = *reinterpret_cast<const uint32_t*>(&h0);
                    hp[24 + nt] = *reinterpret_cast<const uint32_t*>(&h1);
                    hp[32 + nt] = *reinterpret_cast<const uint32_t*>(&h2);
                    hp[40 + nt] = *reinterpret_cast<const uint32_t*>(&h3);
                }
            }
            // fold chunk-local sums into running (m-corrected t)
            {
                float xa, xb, ya, yb;
                upk2(xa, xb, sL0); upk2(ya, yb, tL0);
                const float sl = xa + xb;
                s0 += sl;  t0 += ya + yb + m0 * sl;
                upk2(xa, xb, sL1); upk2(ya, yb, tL1);
                const float sl1v = xa + xb;
                s1 += sl1v;  t1 += ya + yb + m1 * sl1v;
                upk2(xa, xb, sL2); upk2(ya, yb, tL2);
                const float sl2v = xa + xb;
                s2 += sl2v;  t2 += ya + yb + m2 * sl2v;
                upk2(xa, xb, sL3); upk2(ya, yb, tL3);
                const float sl3v = xa + xb;
                s3 += sl3v;  t3 += ya + yb + m3 * sl3v;
            }
            if ((lane & 3) == 0) {
                const int ch = grp * 2 + ci;
                w_s[r0 * 9 + ch]        = m0;
                w_s[(r0 + 8) * 9 + ch]  = m1;
                w_s[(r0 + 16) * 9 + ch] = m2;
                w_s[(r0 + 24) * 9 + ch] = m3;
            }
        }

        // ---- group-local row reductions + publish (m, s, t_u) --------------
        s0 += __shfl_xor_sync(~0u, s0, 1);  s0 += __shfl_xor_sync(~0u, s0, 2);
        t0 += __shfl_xor_sync(~0u, t0, 1);  t0 += __shfl_xor_sync(~0u, t0, 2);
        s1 += __shfl_xor_sync(~0u, s1, 1);  s1 += __shfl_xor_sync(~0u, s1, 2);
        t1 += __shfl_xor_sync(~0u, t1, 1);  t1 += __shfl_xor_sync(~0u, t1, 2);
        s2 += __shfl_xor_sync(~0u, s2, 1);  s2 += __shfl_xor_sync(~0u, s2, 2);
        t2 += __shfl_xor_sync(~0u, t2, 1);  t2 += __shfl_xor_sync(~0u, t2, 2);
        s3 += __shfl_xor_sync(~0u, s3, 1);  s3 += __shfl_xor_sync(~0u, s3, 2);
        t3 += __shfl_xor_sync(~0u, t3, 1);  t3 += __shfl_xor_sync(~0u, t3, 2);
        if ((lane & 3) == 0) {
            float* p0 = mst_s + (size_t)(grp * 128 + r0) * 4;
            p0[0] = m0; p0[1] = s0; p0[2] = t0;
            float* p1 = mst_s + (size_t)(grp * 128 + r0 + 8) * 4;
            p1[0] = m1; p1[1] = s1; p1[2] = t1;
            float* p2 = mst_s + (size_t)(grp * 128 + r0 + 16) * 4;
            p2[0] = m2; p2[1] = s2; p2[2] = t2;
            float* p3 = mst_s + (size_t)(grp * 128 + r0 + 24) * 4;
            p3[0] = m3; p3[1] = s3; p3[2] = t3;
        }
        __syncthreads();   // sync2: mst published

        // ---- merge 4 groups per row (thread = row): Mv, inv, loss only -----
        float lossr = 0.f;
        if (tid < TM) {
            float Mv = -1e30f;
            float mg[4], sg[4], tg[4];
            #pragma unroll
            for (int g = 0; g < 4; g++) {
                const float* p = mst_s + (size_t)(g * 128 + tid) * 4;
                mg[g] = p[0]; sg[g] = p[1]; tg[g] = p[2];
                Mv = fmaxf(Mv, mg[g]);
            }
            float sF = 0.f, tF = 0.f;
            #pragma unroll
            for (int g = 0; g < 4; g++) {
                const float f = ex2f(mg[g] - Mv);
                sF += sg[g] * f; tF += tg[g] * f;
            }
            const float inv = 1.f / sF;
            lossr = (zsq_s[tid] - tF * inv) * LN2;
            mst_s[(size_t)tid * 4 + 3]         = Mv;    // pad slot of grp0 row
            mst_s[(size_t)(128 + tid) * 4 + 3] = inv;   // pad slot of grp1 row
        }
        #pragma unroll
        for (int o = 16; o; o >>= 1) lossr += __shfl_xor_sync(~0u, lossr, o);
        if (wid < 4 && lane == 0) red_s[wid] = lossr;
        __syncthreads();   // sync3: Mv/inv/red_s ready
        if (tid == 0)
            cta_loss += red_s[0] + red_s[1] + red_s[2] + red_s[3];

        // ---- L2-prefetch next z tile (overlaps pass 2) ---------------------
        {
            const int ntile = tile + NCTAS;
            if (ntile < NTILES) {
                const char* pz = reinterpret_cast<const char*>(
                    z4 + (size_t)ntile * 2048) + tid * 256;
                asm volatile("prefetch.global.L2 [%0];" :: "l"(pz));
                asm volatile("prefetch.global.L2 [%0];" :: "l"(pz + 128));
            }
        }

        // ---- PASS 2: q stores, packed e*w, evict-first ---------------------
        {
            float* qt = q_out + (size_t)tile * TM * KC;
            const int c2 = (lane & 3) * 2;
            float Mvj[4], ivj[4];
            #pragma unroll
            for (int j = 0; j < 4; j++) {
                const int r = r0 + j * 8;
                Mvj[j] = mst_s[(size_t)r * 4 + 3];
                ivj[j] = mst_s[(size_t)(128 + r) * 4 + 3];
            }
            #pragma unroll
            for (int ci = 0; ci < 2; ci++) {
                const int ch = grp * 2 + ci;
                const int colb = grp * 128 + ci * 64 + c2;
                const float w0 = ex2f(w_s[r0 * 9 + ch]        - Mvj[0]) * ivj[0];
                const float w1 = ex2f(w_s[(r0 + 8) * 9 + ch]  - Mvj[1]) * ivj[1];
                const float w2 = ex2f(w_s[(r0 + 16) * 9 + ch] - Mvj[2]) * ivj[2];
                const float w3 = ex2f(w_s[(r0 + 24) * 9 + ch] - Mvj[3]) * ivj[3];
                const uint64_t wp0 = pk2(w0, w0);
                const uint64_t wp1 = pk2(w1, w1);
                const uint64_t wp2 = pk2(w2, w2);
                const uint64_t wp3 = pk2(w3, w3);
                #pragma unroll
                for (int nt = 0; nt < 8; nt++) {
                    uint32_t u0, u1, u2, u3;
                    if (ci == 0) {
                        u0 = hp[nt];  u1 = hp[8 + nt];
                        u2 = lds32(estg + (uint32_t)((nt * 2) * 2048));
                        u3 = lds32(estg + (uint32_t)((nt * 2 + 1) * 2048));
                    } else {
                        u0 = hp[16 + nt]; u1 = hp[24 + nt];
                        u2 = hp[32 + nt]; u3 = hp[40 + nt];
                    }
                    const float2 e0 = __half22float2(*reinterpret_cast<const __half2*>(&u0));
                    const float2 e1 = __half22float2(*reinterpret_cast<const __half2*>(&u1));
                    const float2 e2 = __half22float2(*reinterpret_cast<const __half2*>(&u2));
                    const float2 e3 = __half22float2(*reinterpret_cast<const __half2*>(&u3));
                    const uint64_t o0 = mul2(pk2(e0.x, e0.y), wp0);
                    const uint64_t o1 = mul2(pk2(e1.x, e1.y), wp1);
                    const uint64_t o2 = mul2(pk2(e2.x, e2.y), wp2);
                    const uint64_t o3 = mul2(pk2(e3.x, e3.y), wp3);
                    stg_cs64(qt + (size_t)r0 * KC + colb + nt * 8, o0);
                    stg_cs64(qt + (size_t)(r0 + 8) * KC + colb + nt * 8, o1);
                    stg_cs64(qt + (size_t)(r0 + 16) * KC + colb + nt * 8, o2);
                    stg_cs64(qt + (size_t)(r0 + 24) * KC + colb + nt * 8, o3);
                }
            }
        }
    } // tile loop

    if (tid == 0) g_loss_partial[bid] = cta_loss;

    // ---- last-CTA loss finalize (deterministic fixed-order sum) ------------
    __threadfence();
    if (tid == 0) {
        const unsigned int old = atomicAdd(&g_done, 1u);
        *flag_s = (old == (unsigned int)(NCTAS - 1)) ? 1u : 0u;
    }
    __syncthreads();
    if (*flag_s) {
        double a = (tid < NCTAS) ? (double)g_loss_partial[tid] : 0.0;
        #pragma unroll
        for (int o = 16; o; o >>= 1) a += __shfl_xor_sync(~0u, a, o);
        double* dred = reinterpret_cast<double*>(smem + OFF_RED + 128);
        if (lane == 0) dred[wid] = a;
        __syncthreads();
        if (tid == 0) {
            double t = 0.0;
            #pragma unroll
            for (int i = 0; i < 16; i++) t += dred[i];
            if (loss_out) *loss_out = (float)(t / (double)B_ROWS);
            g_done = 0;   // reset for next graph replay
        }
    }
}

// ============================================================================
// Launch
// ============================================================================
extern "C" void kernel_launch(void* const* d_in, const int* in_sizes, int n_in,
                              void* d_out, int out_size) {
    const float* z  = (const float*)d_in[0];
    const float* cc = (const float*)d_in[1];
    float* q = (float*)d_out;

    const long long q_elems = (long long)B_ROWS * KC;  // 67108864
    float* loss_out = ((long long)out_size > q_elems) ? (q + q_elems) : nullptr;

    cudaFuncSetAttribute(soft_kmeans_kernel,
                         cudaFuncAttributeMaxDynamicSharedMemorySize, SMEM_BYTES);
    soft_kmeans_kernel<<<NCTAS, 512, SMEM_BYTES>>>(z, cc, q, loss_out);
}